// round 17
// baseline (speedup 1.0000x reference)
#include <cuda_runtime.h>
#include <cuda_bf16.h>
#include <cstdint>

#define B_ 8
#define N_ 256
#define L_ 48
#define F_ 96
#define LF (L_*F_)
#define NSTRIP 32   // i-strips for k_reduce (8 rows each)
#define GPERS 152   // persistent grid

// k_main smem layout (bytes)
#define ASTRF 104                    // A row stride in floats (416 B)
#define ABUF_BYTES (128*ASTRF*4)     // 53248
#define OFF_A0 0
#define OFF_A1 53248
#define OFF_B  106496                // 96 x 104 bf16 = 19968
#define OFF_BIAS0 126464             // 2304 floats = 9216 B
#define OFF_BIAS1 135680
#define SMEM_TOTAL 144896

// ---------------- scratch (no allocation allowed) ----------------
__device__ float g_rowsum [B_*N_*L_];
__device__ float g_diag   [B_*N_*L_];
__device__ float g_colpart[B_*NSTRIP*N_*L_];
__device__ float g_stripT [B_*NSTRIP*L_];
__device__ float g_stripS [B_*NSTRIP*L_];
__device__ float g_diagA  [B_*N_*F_];
__device__ float g_bi     [B_*N_*F_];
__device__ float g_bjs    [B_*N_*F_];

// ---------------- helpers ----------------
__device__ __forceinline__ void mma_bf16(float* c, const uint32_t* a, const uint32_t* b){
    asm volatile(
        "mma.sync.aligned.m16n8k16.row.col.f32.bf16.bf16.f32 "
        "{%0,%1,%2,%3}, {%4,%5,%6,%7}, {%8,%9}, {%0,%1,%2,%3};"
        : "+f"(c[0]), "+f"(c[1]), "+f"(c[2]), "+f"(c[3])
        : "r"(a[0]), "r"(a[1]), "r"(a[2]), "r"(a[3]), "r"(b[0]), "r"(b[1]));
}
__device__ __forceinline__ uint32_t smem_u32(const void* p){
    uint32_t a;
    asm("{ .reg .u64 t; cvta.to.shared.u64 t, %1; cvt.u32.u64 %0, t; }" : "=r"(a) : "l"(p));
    return a;
}
__device__ __forceinline__ void cp16(uint32_t dst, const void* src){
    asm volatile("cp.async.cg.shared.global [%0], [%1], 16;"
                 :: "r"(dst), "l"(__cvta_generic_to_global(src)) : "memory");
}
#define CP_COMMIT() asm volatile("cp.async.commit_group;" ::: "memory")
#define CP_WAIT0()  asm volatile("cp.async.wait_group 0;" ::: "memory")

__device__ __forceinline__ uint32_t pack_bf2(float2 v){
    __nv_bfloat162 h = __floats2bfloat162_rn(v.x, v.y);   // lo=k, hi=k+1
    return *(uint32_t*)&h;
}
// k-interleave within each 16-col group (B only; same as R10/R16 proven layout)
__device__ __forceinline__ int kpos16(int k){
    return (k & ~15) + (((k & 7) >> 1) << 2) + (((k >> 3) & 1) << 1) + (k & 1);
}

// ================= K0: fused reductions, 2 barriers =================
__global__ __launch_bounds__(384) void k_reduce(const float* __restrict__ x){
    const int istrip = blockIdx.x, b = blockIdx.y;
    const int i0 = istrip*8;
    const int t = threadIdx.x;
    const int q = t/12, lq = (t%12)*4;

    extern __shared__ float smr[];
    float* rp = smr;               // [8][32][49]
    float* rs = rp + 8*32*49;      // [8][48]
    float* dgs = rs + 8*48;        // [8][48]

    float ca[8][4];
    #pragma unroll
    for (int jj = 0; jj < 8; jj++){ ca[jj][0]=0.f; ca[jj][1]=0.f; ca[jj][2]=0.f; ca[jj][3]=0.f; }

    const float* xb = x + ((size_t)b)*N_*N_*L_;

    #pragma unroll
    for (int ii = 0; ii < 8; ii++){
        const float* xr = xb + (size_t)(i0+ii)*N_*L_;
        float r0=0.f, r1=0.f, r2=0.f, r3=0.f;
        #pragma unroll
        for (int jj = 0; jj < 8; jj++){
            float4 v = *(const float4*)(xr + (q + 32*jj)*L_ + lq);
            ca[jj][0]+=v.x; ca[jj][1]+=v.y; ca[jj][2]+=v.z; ca[jj][3]+=v.w;
            r0+=v.x; r1+=v.y; r2+=v.z; r3+=v.w;
        }
        float* rpp = rp + (ii*32 + q)*49 + lq;
        rpp[0]=r0; rpp[1]=r1; rpp[2]=r2; rpp[3]=r3;
    }
    __syncthreads();
    {
        const int ii = t / 48, l = t % 48;
        float s = 0.f;
        #pragma unroll
        for (int qq = 0; qq < 32; qq++) s += rp[(ii*32 + qq)*49 + l];
        const int i = i0 + ii;
        g_rowsum[(b*N_+i)*L_ + l] = s;
        rs[ii*48 + l] = s;
        const float dv = xb[((size_t)i*N_ + i)*L_ + l];
        g_diag[(b*N_+i)*L_ + l] = dv;
        dgs[ii*48 + l] = dv;
    }
    __syncthreads();
    if (t < 48){
        float sT = 0.f, sS = 0.f;
        #pragma unroll
        for (int ii = 0; ii < 8; ii++){ sT += dgs[ii*48 + t]; sS += rs[ii*48 + t]; }
        g_stripT[(b*NSTRIP+istrip)*L_ + t] = sT;
        g_stripS[(b*NSTRIP+istrip)*L_ + t] = sS;
    }
    #pragma unroll
    for (int jj = 0; jj < 8; jj++){
        float* cp = g_colpart + ((size_t)((b*NSTRIP+istrip)*N_ + q + 32*jj))*L_ + lq;
        *(float4*)cp = make_float4(ca[jj][0], ca[jj][1], ca[jj][2], ca[jj][3]);
    }
}

// ================= K1: per-node projections + scalars =================
__global__ __launch_bounds__(96) void k_node(const float* __restrict__ w){
    const int b = blockIdx.y;
    const int n0 = blockIdx.x * 8;
    const int t = threadIdx.x;

    __shared__ float d_[8][48], r_[8][48], c_[8][48];
    __shared__ float tr[48], ts[48];

    for (int idx = t; idx < 8*48; idx += 96){
        const int nn = idx / 48, l = idx % 48;
        const int base = (b*N_ + n0 + nn)*L_ + l;
        d_[nn][l] = g_diag  [base];
        r_[nn][l] = g_rowsum[base];
        float s = 0.f;
        #pragma unroll
        for (int st = 0; st < NSTRIP; st++)
            s += g_colpart[((size_t)((b*NSTRIP+st)*N_ + n0 + nn))*L_ + l];
        c_[nn][l] = s;
    }
    if (t < 48){
        float a = 0.f, s = 0.f;
        #pragma unroll
        for (int st = 0; st < NSTRIP; st++){
            a += g_stripT[(b*NSTRIP+st)*L_ + t];
            s += g_stripS[(b*NSTRIP+st)*L_ + t];
        }
        tr[t] = a; ts[t] = s;
    }
    __syncthreads();

    float aA[8], aJ[8], aI[8];
    #pragma unroll
    for (int nn = 0; nn < 8; nn++){ aA[nn]=0.f; aJ[nn]=0.f; aI[nn]=0.f; }
    float ds = 0.f, sc = 0.f;

    for (int l = 0; l < 48; l++){
        const float* wl = w + l*F_ + t;
        const float w0  = __ldg(wl);
        const float w1  = __ldg(wl +    LF);
        const float w2  = __ldg(wl +  2*LF);
        const float w3  = __ldg(wl +  3*LF);
        const float w4  = __ldg(wl +  4*LF);
        const float w5  = __ldg(wl +  5*LF);
        const float w6  = __ldg(wl +  6*LF);
        const float w7  = __ldg(wl +  7*LF);
        const float w8  = __ldg(wl +  8*LF);
        const float w9  = __ldg(wl +  9*LF);
        const float w10 = __ldg(wl + 10*LF);
        const float w13 = __ldg(wl + 13*LF);
        const float w14 = __ldg(wl + 14*LF);
        const float trl = tr[l], tsl = ts[l];
        ds += trl*w3  + tsl*w4;
        sc += trl*w13 + tsl*w14;
        #pragma unroll
        for (int nn = 0; nn < 8; nn++){
            const float dd = d_[nn][l], rr = r_[nn][l], cc = c_[nn][l];
            aA[nn] += dd*w0 + rr*w1 + cc*w2;
            aJ[nn] += dd*w5 + rr*w6 + cc*w7;
            aI[nn] += dd*w8 + rr*w9 + cc*w10;
        }
    }
    #pragma unroll
    for (int nn = 0; nn < 8; nn++){
        const int o = (b*N_ + n0 + nn)*F_ + t;
        g_diagA[o] = aA[nn] + ds;
        g_bjs  [o] = aJ[nn] + sc;
        g_bi   [o] = aI[nn];
    }
}

// ================= K2: persistent bf16 mma.sync + cp.async double buffer =================
// Tile = 8x16 positions: M=128, N=96, K=96. A in fp32 (cp.async raw), cvt->bf16 in
// mainloop. 32 warps; warp = 1 i-row (M16 covers tj 0..15), N24. One barrier/tile.
__global__ __launch_bounds__(1024, 1)
void k_main(const float* __restrict__ x, const float* __restrict__ w,
            float* __restrict__ out){
    const int tid = threadIdx.x;
    const int bk = blockIdx.x;

    extern __shared__ char smraw[];
    const uint32_t sb = smem_u32(smraw);
    const float* Af[2] = {(const float*)(smraw + OFF_A0), (const float*)(smraw + OFF_A1)};
    __nv_bfloat16* Bb = (__nv_bfloat16*)(smraw + OFF_B);
    const float* biasf[2] = {(const float*)(smraw + OFF_BIAS0), (const float*)(smraw + OFF_BIAS1)};

    // ---- stage B once (bf16, k-interleaved) ----
    {
        const float* w12g = w + 12*LF;
        const float* w11g = w + 11*LF;
        for (int idx = tid; idx < 96*96; idx += 1024){
            const int k = idx / 96, f = idx % 96;
            const float v = (k < 48) ? __ldg(w12g + k*F_ + f) : __ldg(w11g + (k-48)*F_ + f);
            Bb[f*ASTRF + kpos16(k)] = __float2bfloat16(v);
        }
    }

    // ---- precompute per-thread cp.async chunk decode (tile-independent) ----
    int hq[3], tiq[3], tjq[3], c4q[3];
    uint32_t dofsq[3];
    #pragma unroll
    for (int q = 0; q < 3; q++){
        const int idx = tid + q*1024;           // 0..3071
        const int h = (idx >= 1536) ? 1 : 0;
        const int ix = idx - h*1536;
        const int p = ix / 12, c = ix % 12;
        hq[q] = h; tiq[q] = p >> 4; tjq[q] = p & 15; c4q[q] = c*4;
        dofsq[q] = (uint32_t)((p*ASTRF + h*48 + c*4) * 4);
    }
    int brow = 0, bc4 = 0, bkind = 0;
    uint32_t bdofs = 0;
    if (tid < 576){
        if (tid < 192){ bkind = 0; brow = tid/24; bc4 = (tid%24)*4; bdofs = (uint32_t)((brow*96 + bc4)*4); }
        else { const int ix = tid - 192; bkind = 1; brow = ix/24; bc4 = (ix%24)*4; bdofs = (uint32_t)((768 + brow*96 + bc4)*4); }
    }

    // tiles: 4096 total = 8 b x 32 it x 16 jt; i0 = it*8, j0 = jt*16
    const int base = bk*26 + (bk < 144 ? bk : 144);
    const int cnt  = 26 + (bk < 144 ? 1 : 0);

    auto issue = [&](int tl, int bf){
        const int b = tl >> 9, r = tl & 511;
        const int i0 = (r >> 4)*8, j0 = (r & 15)*16;
        const float* xb = x + ((size_t)b)*N_*N_*L_;
        const uint32_t abase = sb + (bf ? OFF_A1 : OFF_A0);
        #pragma unroll
        for (int q = 0; q < 3; q++){
            const int ti = tiq[q], tj = tjq[q];
            const float* src = hq[q]
                ? xb + ((size_t)(j0+tj)*N_ + (i0+ti))*L_ + c4q[q]
                : xb + ((size_t)(i0+ti)*N_ + (j0+tj))*L_ + c4q[q];
            cp16(abase + dofsq[q], src);
        }
        if (tid < 576){
            const uint32_t bbase = sb + (bf ? OFF_BIAS1 : OFF_BIAS0);
            const float* src = bkind
                ? (g_bjs + (b*N_ + j0 + brow)*F_ + bc4)
                : (g_bi  + (b*N_ + i0 + brow)*F_ + bc4);
            cp16(bbase + bdofs, src);
        }
        CP_COMMIT();
    };

    // prologue
    issue(base, 0);
    CP_WAIT0();
    __syncthreads();

    // ---- warp mapping: 32 warps = 8 mw x 4 nw; warp covers i-row mw, N24 ----
    const int wid = tid >> 5, lane = tid & 31;
    const int mw = wid >> 2, nw = wid & 3;
    const int g = lane >> 2, t4 = lane & 3;
    const int nbv = nw*24;
    const int arow0 = (mw*16 + g)*ASTRF;
    const int arow1 = (mw*16 + g + 8)*ASTRF;

    const uint2* B8 = (const uint2*)Bb;   // row stride 26 (uint2 = 4 bf16)

    int cur = 0;
    for (int s = 0; s < cnt; s++){
        const int tl = base + s;
        const int b = tl >> 9, r = tl & 511;
        const int i0 = (r >> 4)*8, j0 = (r & 15)*16;
        const bool hasNext = (s + 1 < cnt);

        if (hasNext) issue(tl + 1, cur ^ 1);

        // ---- MMA mainloop: 6 k16 steps ----
        const float* As = Af[cur];
        float acc[3][4];
        #pragma unroll
        for (int tl2 = 0; tl2 < 3; tl2++)
            #pragma unroll
            for (int qq = 0; qq < 4; qq++) acc[tl2][qq] = 0.f;

        #pragma unroll
        for (int ks = 0; ks < 6; ks++){
            const int kc = ks*16 + t4*2;
            float2 u0 = *(const float2*)(As + arow0 + kc);
            float2 u1 = *(const float2*)(As + arow1 + kc);
            float2 u2 = *(const float2*)(As + arow0 + kc + 8);
            float2 u3 = *(const float2*)(As + arow1 + kc + 8);
            uint32_t a[4];
            a[0] = pack_bf2(u0); a[1] = pack_bf2(u1);
            a[2] = pack_bf2(u2); a[3] = pack_bf2(u3);
            uint32_t bfr[3][2];
            #pragma unroll
            for (int tl2 = 0; tl2 < 3; tl2++){
                uint2 qv = B8[(size_t)(nbv + tl2*8 + g)*26 + ks*4 + t4];
                bfr[tl2][0] = qv.x; bfr[tl2][1] = qv.y;
            }
            #pragma unroll
            for (int tl2 = 0; tl2 < 3; tl2++)
                mma_bf16(acc[tl2], a, bfr[tl2]);
        }

        // ---- epilogue ----
        const float* bis   = biasf[cur];
        const float* bjs_s = biasf[cur] + 768;
        const int gi = i0 + mw;
        const float* irow = bis + mw*F_;
        const float* drow = g_diagA + ((size_t)(b*N_ + gi))*F_;
        #pragma unroll
        for (int half = 0; half < 2; half++){
            const int tj = g + half*8;
            const int gj = j0 + tj;
            const bool dg = (gi == gj);
            float* orow = out + (((size_t)(b*N_ + gi))*N_ + gj)*F_;
            const float* jrow = bjs_s + tj*F_;
            #pragma unroll
            for (int tl2 = 0; tl2 < 3; tl2++){
                const int f = nbv + tl2*8 + 2*t4;
                float v0 = acc[tl2][half*2+0] + irow[f]   + jrow[f];
                float v1 = acc[tl2][half*2+1] + irow[f+1] + jrow[f+1];
                if (dg){ v0 += __ldg(drow + f); v1 += __ldg(drow + f + 1); }
                *(float2*)(orow + f) = make_float2(v0, v1);
            }
        }

        if (hasNext) CP_WAIT0();
        __syncthreads();
        cur ^= 1;
    }
}

// ---------------- launch ----------------
extern "C" void kernel_launch(void* const* d_in, const int* in_sizes, int n_in,
                              void* d_out, int out_size){
    const float* x = (const float*)d_in[0];
    const float* w = (const float*)d_in[1];
    float* out = (float*)d_out;
    (void)in_sizes; (void)n_in; (void)out_size;

    const size_t smr = (size_t)(8*32*49 + 2*8*48) * sizeof(float);
    cudaFuncSetAttribute(k_reduce, cudaFuncAttributeMaxDynamicSharedMemorySize, (int)smr);
    k_reduce<<<dim3(NSTRIP, B_), 384, smr>>>(x);

    k_node<<<dim3(32, B_), 96>>>(w);

    cudaFuncSetAttribute(k_main, cudaFuncAttributeMaxDynamicSharedMemorySize, SMEM_TOTAL);
    k_main<<<GPERS, 1024, SMEM_TOTAL>>>(x, w, out);
}